// round 13
// baseline (speedup 1.0000x reference)
#include <cuda_runtime.h>

#define BB 4
#define HH 256
#define WW 256
#define NN 256

// Scratch (static __device__ arrays: allocation-free, zero-initialized).
__device__ float4 g_gf[BB * HH * WW];  // (ygrad, xgrad, gw, 0) per pixel
__device__ double g_part[256];
__device__ unsigned g_ctr = 0;

// ---------------------------------------------------------------------------
// Stage 1: separable 13x13 edge conv, both modes (signed + abs), 16-row tiles
// (grid = 8 x 16 x 4 = 512 blocks). V-pass emits 2 adjacent rows per thread
// from one 14-tap window. FP32-immediate coefficients.
// ---------------------------------------------------------------------------
__global__ __launch_bounds__(256) void conv_kernel(const float* __restrict__ x) {
    constexpr float KG[13] = {
        0.00221820f, 0.00877313f, 0.02702315f, 0.06482518f, 0.12110938f,
        0.17621311f, 0.19967563f, 0.17621311f, 0.12110938f, 0.06482518f,
        0.02702315f, 0.00877313f, 0.00221820f};
    constexpr float KD[13] = {
        0.00332730f, 0.01096641f, 0.02702315f, 0.04861888f, 0.06055469f,
        0.04405328f, 0.00000000f, -0.04405328f, -0.06055469f, -0.04861888f,
        -0.02702315f, -0.01096641f, -0.00332730f};

    __shared__ float s_in[28][48];  // 16+12 halo rows, 32+12 halo cols
    __shared__ float s_hg[28][32];
    __shared__ float s_hd[28][32];
    __shared__ float s_ag[28][32];
    __shared__ float s_ad[28][32];

    const int b = blockIdx.z;
    const int ty0 = blockIdx.y * 16, tx0 = blockIdx.x * 32;
    const float* xb = x + b * HH * WW;
    const int t = threadIdx.x;

    // 28x44 input tile with 6-px halo, zero padding ('SAME').
    for (int idx = t; idx < 28 * 44; idx += 256) {
        int iy = idx / 44, ix = idx % 44;
        int gy = ty0 + iy - 6, gx = tx0 + ix - 6;
        float v = 0.0f;
        if ((unsigned)gy < HH && (unsigned)gx < WW) v = xb[gy * WW + gx];
        s_in[iy][ix] = v;
    }
    __syncthreads();

    // Horizontal pass: 28x32 positions, 4 accumulators.
    for (int idx = t; idx < 28 * 32; idx += 256) {
        int iy = idx >> 5, ix = idx & 31;
        float hg = 0.f, hd = 0.f, ag = 0.f, ad = 0.f;
#pragma unroll
        for (int l = 0; l < 13; l++) {
            float v = s_in[iy][ix + l];
            float a = fabsf(v);
            hg = fmaf(v, KG[l], hg);
            hd = fmaf(v, KD[l], hd);
            ag = fmaf(a, KG[l], ag);
            ad = fmaf(a, KD[l], ad);
        }
        s_hg[iy][ix] = hg;
        s_hd[iy][ix] = hd;
        s_ag[iy][ix] = ag;
        s_ad[iy][ix] = ad;
    }
    __syncthreads();

    // Vertical pass: thread (ix, r0) emits rows r0 and r0+1 from a shared
    // 14-tap window (row r0: taps k at K[k]; row r0+1: taps k at K[k-1]).
    {
        const int ix = t & 31;
        const int r0 = (t >> 5) * 2;  // 0,2,...,14
        float c0a = 0.f, c1a = 0.f, w0a = 0.f, w1a = 0.f;
        float c0b = 0.f, c1b = 0.f, w0b = 0.f, w1b = 0.f;
#pragma unroll
        for (int k = 0; k < 13; k++) {
            float vg = s_hg[r0 + k][ix];
            float vd = s_hd[r0 + k][ix];
            float va = s_ag[r0 + k][ix];
            float vb = s_ad[r0 + k][ix];
            c0a = fmaf(vg, KD[k], c0a);
            c1a = fmaf(vd, KG[k], c1a);
            w0a = fmaf(va, KD[k], w0a);
            w1a = fmaf(vb, KG[k], w1a);
            if (k >= 1) {
                c0b = fmaf(vg, KD[k - 1], c0b);
                c1b = fmaf(vd, KG[k - 1], c1b);
                w0b = fmaf(va, KD[k - 1], w0b);
                w1b = fmaf(vb, KG[k - 1], w1b);
            }
        }
        {
            float vg = s_hg[r0 + 13][ix];
            float vd = s_hd[r0 + 13][ix];
            float va = s_ag[r0 + 13][ix];
            float vb = s_ad[r0 + 13][ix];
            c0b = fmaf(vg, KD[12], c0b);
            c1b = fmaf(vd, KG[12], c1b);
            w0b = fmaf(va, KD[12], w0b);
            w1b = fmaf(vb, KG[12], w1b);
        }
        int o = (b * HH + ty0 + r0) * WW + tx0 + ix;
        g_gf[o] = make_float4(10.0f * c0a, 10.0f * c1a, 10.0f * (w0a + w1a), 0.0f);
        g_gf[o + WW] = make_float4(10.0f * c0b, 10.0f * c1b, 10.0f * (w0b + w1b), 0.0f);
    }
}

// ---------------------------------------------------------------------------
// Stage 2 (fused): snake + render + MSE + final reduce. grid = (64, BB).
// Each block (tile, b) REDUNDANTLY recomputes the full snake for batch b
// (256 threads = 256 nodes; identical inputs -> identical FP sequence in all
// 64 tile-blocks -> deterministic), then renders its own 32x32 tile from the
// register-resident node state. This removes the snake->render kernel
// boundary and the g_py/g_px/g_wd global round-trip.
// Snake uses software-pipelined gathers: corner set (4 x float4) carried in
// registers, loaded at np in iter s, consumed for the width force of step s
// (committed in iter s+1) and the position force of step s+1. Bit-exact vs
// the reference schedule.
// ---------------------------------------------------------------------------
__device__ __forceinline__ void bilin_setup(float y, float x, int& off, float& ty, float& tx) {
    y = fminf(fmaxf(y, 0.0f), 254.999f);  // H - 1.001
    x = fminf(fmaxf(x, 0.0f), 254.999f);
    float fy = floorf(y), fx = floorf(x);
    off = (int)fy * WW + (int)fx;
    ty = y - fy;
    tx = x - fx;
}

__global__ __launch_bounds__(256) void snake_render_kernel(
    const float* __restrict__ pred, const float* __restrict__ node_pos,
    const float* __restrict__ widths, float* __restrict__ out) {
    __shared__ float2 spp[2][NN];  // (y, x)
    __shared__ float sww[2][NN];
    __shared__ float cy[NN], cx[NN], cw[NN];
    __shared__ int cnt;
    __shared__ float wsum[8];

    const int b = blockIdx.y;
    const int tile = blockIdx.x;
    const int ty0 = (tile >> 3) * 32, tx0 = (tile & 7) * 32;
    const int t = threadIdx.x;
    const int tx = t & 31, tyb = t >> 5;  // thread owns rows tyb + {0,8,16,24}

    // Prefetch this tile's pred pixels early (independent of snake).
    float pv[4];
#pragma unroll
    for (int r = 0; r < 4; r++) {
        int gy = ty0 + tyb + 8 * r, gx = tx0 + tx;
        pv[r] = pred[(b * HH + gy) * WW + gx];
    }
    if (t == 0) cnt = 0;

    // ---------------- Snake (node i = t of batch b) ----------------
    const int i = t;
    const int im1 = max(i - 1, 0), ip1 = min(i + 1, NN - 1);
    const int im2 = max(i - 2, 0), ip2 = min(i + 2, NN - 1);
    const bool lo = (i == 0), hi = (i == NN - 1);

    float2 p = make_float2(node_pos[(b * NN + i) * 2 + 0],
                           node_pos[(b * NN + i) * 2 + 1]);
    float wi = widths[b * NN + i];
    spp[0][i] = p;
    sww[0][i] = wi;
    const float4* gf = g_gf + b * HH * WW;

    // Preload corners at p(0).
    int off; float ty, txf;
    bilin_setup(p.x, p.y, off, ty, txf);
    float4 q00 = gf[off], q01 = gf[off + 1];
    float4 q10 = gf[off + WW], q11 = gf[off + WW + 1];
    __syncthreads();

    int cur = 0;
#pragma unroll 1
    for (int s = 0; s < 50; s++) {
        const int nxt = cur ^ 1;

        float2 pm1 = spp[cur][im1], pp1 = spp[cur][ip1];
        float2 pm2 = spp[cur][im2], pp2 = spp[cur][ip2];
        float wm1 = sww[cur][im1], wp1 = sww[cur][ip1];

        float w00 = (1.f - ty) * (1.f - txf), w01 = (1.f - ty) * txf;
        float w10 = ty * (1.f - txf), w11 = ty * txf;

        // Commit w(s) [deferred one iteration; corners already in regs].
        if (s > 0) {
            float fw = q00.z * w00 + q01.z * w01 + q10.z * w10 + q11.z * w11;
            float d2w = wm1 - 2.f * wi + wp1;
            float nwi = wi + 0.1f * (0.01f * d2w + fw);
            wi = fminf(fmaxf(nwi, 0.0f), 15.0f);
        }
        sww[nxt][i] = wi;

        float fY = q00.x * w00 + q01.x * w01 + q10.x * w10 + q11.x * w11;
        float fX = q00.y * w00 + q01.y * w01 + q10.y * w10 + q11.y * w11;

        // d2/d4 via clamped 5-point stencil; boundary folds to neighbors.
        float a1y = lo ? pp1.x : p.x, a1x = lo ? pp1.y : p.y;
        float b0y = hi ? pm1.x : p.x, b0x = hi ? pm1.y : p.y;
        float d2ym = pm2.x - 2.f * pm1.x + a1y;
        float d2xm = pm2.y - 2.f * pm1.y + a1x;
        float d2yc = pm1.x - 2.f * p.x + pp1.x;
        float d2xc = pm1.y - 2.f * p.y + pp1.y;
        float d2yp = b0y - 2.f * pp1.x + pp2.x;
        float d2xp = b0x - 2.f * pp1.y + pp2.y;
        float d4y = d2ym - 2.f * d2yc + d2yp;
        float d4x = d2xm - 2.f * d2xc + d2xp;

        float npy = p.x + 0.1f * (0.01f * d2yc - 0.005f * d4y + fY);
        float npx = p.y + 0.1f * (0.01f * d2xc - 0.005f * d4x + fX);
        npy = fminf(fmaxf(npy, 0.0f), 255.0f);  // H-1
        npx = fminf(fmaxf(npx, 0.0f), 255.0f);
        p = make_float2(npy, npx);
        spp[nxt][i] = p;

        // Issue the gather at p(s+1) = np; consumed next iteration.
        bilin_setup(npy, npx, off, ty, txf);
        q00 = gf[off]; q01 = gf[off + 1];
        q10 = gf[off + WW]; q11 = gf[off + WW + 1];

        __syncthreads();
        cur = nxt;
    }

    // Epilogue: commit w(50) using C_50 (just loaded) and w(49).
    {
        float wm1 = sww[cur][im1], wp1 = sww[cur][ip1];
        float w00 = (1.f - ty) * (1.f - txf), w01 = (1.f - ty) * txf;
        float w10 = ty * (1.f - txf), w11 = ty * txf;
        float fw = q00.z * w00 + q01.z * w01 + q10.z * w10 + q11.z * w11;
        float d2w = wm1 - 2.f * wi + wp1;
        float nwi = wi + 0.1f * (0.01f * d2w + fw);
        wi = fminf(fmaxf(nwi, 0.0f), 15.0f);
    }
    // Node state for node t now in registers: p.x (y), p.y (x), wi (width).

    // ---------------- Candidate cull (this tile) ----------------
    {
        float m = wi + 15.0f;
        // Closest point of the tile rect to the node, exact distance test.
        float ry = fminf(fmaxf(p.x, (float)ty0), (float)(ty0 + 31));
        float rx = fminf(fmaxf(p.y, (float)tx0), (float)(tx0 + 31));
        float ddy = p.x - ry, ddx = p.y - rx;
        if (fmaf(ddy, ddy, ddx * ddx) < m * m) {
            int k = atomicAdd(&cnt, 1);
            cy[k] = p.x;
            cx[k] = p.y;
            cw[k] = wi;
        }
    }
    __syncthreads();

    // ---------------- Render + MSE ----------------
    const int n = cnt;
    const float xf = (float)(tx0 + tx);
    float mins[4];
    float yfs[4];
#pragma unroll
    for (int r = 0; r < 4; r++) {
        yfs[r] = (float)(ty0 + tyb + 8 * r);
        mins[r] = 15.0f;  // DMAX: culled nodes cannot beat 15 in this tile
    }
    for (int j = 0; j < n; j++) {
        float dx = xf - cx[j];
        float dx2 = dx * dx;
        float pyj = cy[j], wj = cw[j];
#pragma unroll
        for (int r = 0; r < 4; r++) {
            float dy = yfs[r] - pyj;
            float r2 = fmaf(dy, dy, dx2);
            r2 = fmaxf(r2, 1e-18f);
            float d = fmaf(r2, rsqrtf(r2), -wj);  // sqrt(r2) - w
            mins[r] = fminf(mins[r], d);
        }
    }

    float acc = 0.0f;
#pragma unroll
    for (int r = 0; r < 4; r++) {
        float dm = fminf(fmaxf(mins[r], 0.0f), 15.0f);
        float e = pv[r] - dm;
        acc = fmaf(e, e, acc);
    }
#pragma unroll
    for (int o = 16; o > 0; o >>= 1) acc += __shfl_xor_sync(0xffffffffu, acc, o);
    if ((t & 31) == 0) wsum[t >> 5] = acc;
    __syncthreads();
    if (t == 0) {
        float s = 0.0f;
#pragma unroll
        for (int k = 0; k < 8; k++) s += wsum[k];
        g_part[b * 64 + tile] = (double)s;
    }

    // Last-block final reduction (fixed order -> deterministic).
    __shared__ double sd[256];
    __shared__ unsigned is_last;
    __threadfence();
    if (t == 0) is_last = (atomicAdd(&g_ctr, 1u) == 255u);
    __syncthreads();
    if (!is_last) return;
    __threadfence();
    sd[t] = g_part[t];
    __syncthreads();
    for (int o = 128; o > 0; o >>= 1) {
        if (t < o) sd[t] += sd[t + o];
        __syncthreads();
    }
    if (t == 0) {
        out[0] = (float)(sd[0] / (double)(BB * HH * WW));
        g_ctr = 0;  // reset for next graph replay
    }
}

extern "C" void kernel_launch(void* const* d_in, const int* in_sizes, int n_in,
                              void* d_out, int out_size) {
    const float* pred = (const float*)d_in[0];      // (4,1,256,256)
    const float* node_pos = (const float*)d_in[1];  // (4,256,2)
    const float* widths = (const float*)d_in[2];    // (4,256)
    (void)in_sizes; (void)n_in; (void)out_size;

    conv_kernel<<<dim3(8, 16, BB), 256>>>(pred);
    snake_render_kernel<<<dim3(64, BB), 256>>>(pred, node_pos, widths, (float*)d_out);
}

// round 14
// speedup vs baseline: 1.4119x; 1.4119x over previous
#include <cuda_runtime.h>

#define BB 4
#define HH 256
#define WW 256
#define NN 256

// Scratch (static __device__ arrays: allocation-free, zero-initialized).
__device__ float4 g_gf[BB * HH * WW];  // (ygrad, xgrad, gw, 0) per pixel
__device__ float  g_py[BB * NN], g_px[BB * NN], g_wd[BB * NN];
__device__ double g_part[256];
__device__ unsigned g_ctr = 0;

// ---------------------------------------------------------------------------
// Stage 1: separable 13x13 edge conv, both modes (signed + abs), 16-row tiles
// (grid = 8 x 16 x 4 = 512 blocks; measured 7.9us). V-pass emits 2 adjacent
// rows per thread from one 14-tap window. FP32-immediate coefficients.
// ---------------------------------------------------------------------------
__global__ __launch_bounds__(256) void conv_kernel(const float* __restrict__ x) {
    constexpr float KG[13] = {
        0.00221820f, 0.00877313f, 0.02702315f, 0.06482518f, 0.12110938f,
        0.17621311f, 0.19967563f, 0.17621311f, 0.12110938f, 0.06482518f,
        0.02702315f, 0.00877313f, 0.00221820f};
    constexpr float KD[13] = {
        0.00332730f, 0.01096641f, 0.02702315f, 0.04861888f, 0.06055469f,
        0.04405328f, 0.00000000f, -0.04405328f, -0.06055469f, -0.04861888f,
        -0.02702315f, -0.01096641f, -0.00332730f};

    __shared__ float s_in[28][48];  // 16+12 halo rows, 32+12 halo cols
    __shared__ float s_hg[28][32];
    __shared__ float s_hd[28][32];
    __shared__ float s_ag[28][32];
    __shared__ float s_ad[28][32];

    const int b = blockIdx.z;
    const int ty0 = blockIdx.y * 16, tx0 = blockIdx.x * 32;
    const float* xb = x + b * HH * WW;
    const int t = threadIdx.x;

    // 28x44 input tile with 6-px halo, zero padding ('SAME').
    for (int idx = t; idx < 28 * 44; idx += 256) {
        int iy = idx / 44, ix = idx % 44;
        int gy = ty0 + iy - 6, gx = tx0 + ix - 6;
        float v = 0.0f;
        if ((unsigned)gy < HH && (unsigned)gx < WW) v = xb[gy * WW + gx];
        s_in[iy][ix] = v;
    }
    __syncthreads();

    // Horizontal pass: 28x32 positions, 4 accumulators.
    for (int idx = t; idx < 28 * 32; idx += 256) {
        int iy = idx >> 5, ix = idx & 31;
        float hg = 0.f, hd = 0.f, ag = 0.f, ad = 0.f;
#pragma unroll
        for (int l = 0; l < 13; l++) {
            float v = s_in[iy][ix + l];
            float a = fabsf(v);
            hg = fmaf(v, KG[l], hg);
            hd = fmaf(v, KD[l], hd);
            ag = fmaf(a, KG[l], ag);
            ad = fmaf(a, KD[l], ad);
        }
        s_hg[iy][ix] = hg;
        s_hd[iy][ix] = hd;
        s_ag[iy][ix] = ag;
        s_ad[iy][ix] = ad;
    }
    __syncthreads();

    // Vertical pass: thread (ix, r0) emits rows r0 and r0+1 from a shared
    // 14-tap window (row r0: taps k at K[k]; row r0+1: taps k at K[k-1]).
    {
        const int ix = t & 31;
        const int r0 = (t >> 5) * 2;  // 0,2,...,14
        float c0a = 0.f, c1a = 0.f, w0a = 0.f, w1a = 0.f;
        float c0b = 0.f, c1b = 0.f, w0b = 0.f, w1b = 0.f;
#pragma unroll
        for (int k = 0; k < 13; k++) {
            float vg = s_hg[r0 + k][ix];
            float vd = s_hd[r0 + k][ix];
            float va = s_ag[r0 + k][ix];
            float vb = s_ad[r0 + k][ix];
            c0a = fmaf(vg, KD[k], c0a);
            c1a = fmaf(vd, KG[k], c1a);
            w0a = fmaf(va, KD[k], w0a);
            w1a = fmaf(vb, KG[k], w1a);
            if (k >= 1) {
                c0b = fmaf(vg, KD[k - 1], c0b);
                c1b = fmaf(vd, KG[k - 1], c1b);
                w0b = fmaf(va, KD[k - 1], w0b);
                w1b = fmaf(vb, KG[k - 1], w1b);
            }
        }
        {
            float vg = s_hg[r0 + 13][ix];
            float vd = s_hd[r0 + 13][ix];
            float va = s_ag[r0 + 13][ix];
            float vb = s_ad[r0 + 13][ix];
            c0b = fmaf(vg, KD[12], c0b);
            c1b = fmaf(vd, KG[12], c1b);
            w0b = fmaf(va, KD[12], w0b);
            w1b = fmaf(vb, KG[12], w1b);
        }
        int o = (b * HH + ty0 + r0) * WW + tx0 + ix;
        g_gf[o] = make_float4(10.0f * c0a, 10.0f * c1a, 10.0f * (w0a + w1a), 0.0f);
        g_gf[o + WW] = make_float4(10.0f * c0b, 10.0f * c1b, 10.0f * (w0b + w1b), 0.0f);
    }
}

// ---------------------------------------------------------------------------
// Stage 2: snake, software-pipelined gathers + cell-reuse. One block per
// batch, one thread per node. Corner set (4 x float4) carried in registers;
// reloaded ONLY when the bilinear cell changes (~20-30% of node-steps) —
// bit-exact, and predicated-off lanes generate no L1 wavefronts (the snake's
// true bottleneck: scattered lanes cost ~1 wavefront per lane per gather).
// ---------------------------------------------------------------------------
__device__ __forceinline__ void bilin_setup(float y, float x, int& off, float& ty, float& tx) {
    y = fminf(fmaxf(y, 0.0f), 254.999f);  // H - 1.001
    x = fminf(fmaxf(x, 0.0f), 254.999f);
    float fy = floorf(y), fx = floorf(x);
    off = (int)fy * WW + (int)fx;
    ty = y - fy;
    tx = x - fx;
}

__global__ __launch_bounds__(256) void snake_kernel(const float* __restrict__ node_pos,
                                                    const float* __restrict__ widths) {
    __shared__ float2 spp[2][NN];  // (y, x)
    __shared__ float sww[2][NN];
    const int b = blockIdx.x;
    const int i = threadIdx.x;
    const int im1 = max(i - 1, 0), ip1 = min(i + 1, NN - 1);
    const int im2 = max(i - 2, 0), ip2 = min(i + 2, NN - 1);
    const bool lo = (i == 0), hi = (i == NN - 1);

    float2 p = make_float2(node_pos[(b * NN + i) * 2 + 0],
                           node_pos[(b * NN + i) * 2 + 1]);
    float wi = widths[b * NN + i];
    spp[0][i] = p;
    sww[0][i] = wi;
    const float4* gf = g_gf + b * HH * WW;

    // Preload corners at p(0).
    int off; float ty, tx;
    bilin_setup(p.x, p.y, off, ty, tx);
    float4 q00 = gf[off], q01 = gf[off + 1];
    float4 q10 = gf[off + WW], q11 = gf[off + WW + 1];
    __syncthreads();

    int cur = 0;
#pragma unroll 1
    for (int s = 0; s < 50; s++) {
        const int nxt = cur ^ 1;

        float2 pm1 = spp[cur][im1], pp1 = spp[cur][ip1];
        float2 pm2 = spp[cur][im2], pp2 = spp[cur][ip2];
        float wm1 = sww[cur][im1], wp1 = sww[cur][ip1];

        float w00 = (1.f - ty) * (1.f - tx), w01 = (1.f - ty) * tx;
        float w10 = ty * (1.f - tx), w11 = ty * tx;

        // Commit w(s) [deferred one iteration; corners already in regs].
        if (s > 0) {
            float fw = q00.z * w00 + q01.z * w01 + q10.z * w10 + q11.z * w11;
            float d2w = wm1 - 2.f * wi + wp1;
            float nwi = wi + 0.1f * (0.01f * d2w + fw);
            wi = fminf(fmaxf(nwi, 0.0f), 15.0f);
        }
        sww[nxt][i] = wi;

        float fY = q00.x * w00 + q01.x * w01 + q10.x * w10 + q11.x * w11;
        float fX = q00.y * w00 + q01.y * w01 + q10.y * w10 + q11.y * w11;

        // d2/d4 via clamped 5-point stencil; boundary folds to neighbors.
        float a1y = lo ? pp1.x : p.x, a1x = lo ? pp1.y : p.y;
        float b0y = hi ? pm1.x : p.x, b0x = hi ? pm1.y : p.y;
        float d2ym = pm2.x - 2.f * pm1.x + a1y;
        float d2xm = pm2.y - 2.f * pm1.y + a1x;
        float d2yc = pm1.x - 2.f * p.x + pp1.x;
        float d2xc = pm1.y - 2.f * p.y + pp1.y;
        float d2yp = b0y - 2.f * pp1.x + pp2.x;
        float d2xp = b0x - 2.f * pp1.y + pp2.y;
        float d4y = d2ym - 2.f * d2yc + d2yp;
        float d4x = d2xm - 2.f * d2xc + d2xp;

        float npy = p.x + 0.1f * (0.01f * d2yc - 0.005f * d4y + fY);
        float npx = p.y + 0.1f * (0.01f * d2xc - 0.005f * d4x + fX);
        npy = fminf(fmaxf(npy, 0.0f), 255.0f);  // H-1
        npx = fminf(fmaxf(npx, 0.0f), 255.0f);
        p = make_float2(npy, npx);
        spp[nxt][i] = p;

        // Corners for p(s+1): reload only if the bilinear cell changed
        // (bit-exact; saves ~70-80% of gather wavefronts).
        int noff; float nty, ntx;
        bilin_setup(npy, npx, noff, nty, ntx);
        if (noff != off) {
            q00 = gf[noff]; q01 = gf[noff + 1];
            q10 = gf[noff + WW]; q11 = gf[noff + WW + 1];
            off = noff;
        }
        ty = nty;
        tx = ntx;

        __syncthreads();
        cur = nxt;
    }

    // Epilogue: commit w(50) using the current corners and w(49).
    {
        float wm1 = sww[cur][im1], wp1 = sww[cur][ip1];
        float w00 = (1.f - ty) * (1.f - tx), w01 = (1.f - ty) * tx;
        float w10 = ty * (1.f - tx), w11 = ty * tx;
        float fw = q00.z * w00 + q01.z * w01 + q10.z * w10 + q11.z * w11;
        float d2w = wm1 - 2.f * wi + wp1;
        float nwi = wi + 0.1f * (0.01f * d2w + fw);
        g_wd[b * NN + i] = fminf(fmaxf(nwi, 0.0f), 15.0f);
    }
    g_py[b * NN + i] = p.x;
    g_px[b * NN + i] = p.y;
}

// ---------------------------------------------------------------------------
// Stage 3: gather render + fused MSE + final reduction. grid = (64, BB) = 256
// blocks, one per 32x32 tile. Exact circle-rect culling (excluded nodes give
// d >= 15 = clip ceiling); fmin order-independent -> deterministic.
// ---------------------------------------------------------------------------
__global__ __launch_bounds__(256) void render_kernel(const float* __restrict__ pred,
                                                     float* __restrict__ out) {
    __shared__ float cy[NN], cx[NN], cw[NN];
    __shared__ int cnt;
    __shared__ float wsum[8];

    const int b = blockIdx.y;
    const int tile = blockIdx.x;
    const int ty0 = (tile >> 3) * 32, tx0 = (tile & 7) * 32;
    const int t = threadIdx.x;
    const int tx = t & 31, tyb = t >> 5;  // thread owns rows tyb + {0,8,16,24}

    // Fetch the 4 pred pixels early.
    float pv[4];
#pragma unroll
    for (int r = 0; r < 4; r++) {
        int gy = ty0 + tyb + 8 * r, gx = tx0 + tx;
        pv[r] = pred[(b * HH + gy) * WW + gx];
    }
    if (t == 0) cnt = 0;
    __syncthreads();
    {
        float py = g_py[b * NN + t];
        float px = g_px[b * NN + t];
        float w = g_wd[b * NN + t];
        float m = w + 15.0f;
        float ry = fminf(fmaxf(py, (float)ty0), (float)(ty0 + 31));
        float rx = fminf(fmaxf(px, (float)tx0), (float)(tx0 + 31));
        float ddy = py - ry, ddx = px - rx;
        if (fmaf(ddy, ddy, ddx * ddx) < m * m) {
            int k = atomicAdd(&cnt, 1);
            cy[k] = py;
            cx[k] = px;
            cw[k] = w;
        }
    }
    __syncthreads();

    const int n = cnt;
    const float xf = (float)(tx0 + tx);
    float mins[4];
    float yfs[4];
#pragma unroll
    for (int r = 0; r < 4; r++) {
        yfs[r] = (float)(ty0 + tyb + 8 * r);
        mins[r] = 15.0f;  // DMAX: culled nodes cannot beat 15 in this tile
    }
    for (int j = 0; j < n; j++) {
        float dx = xf - cx[j];
        float dx2 = dx * dx;
        float pyj = cy[j], wj = cw[j];
#pragma unroll
        for (int r = 0; r < 4; r++) {
            float dy = yfs[r] - pyj;
            float r2 = fmaf(dy, dy, dx2);
            r2 = fmaxf(r2, 1e-18f);
            float d = fmaf(r2, rsqrtf(r2), -wj);  // sqrt(r2) - w
            mins[r] = fminf(mins[r], d);
        }
    }

    float acc = 0.0f;
#pragma unroll
    for (int r = 0; r < 4; r++) {
        float dm = fminf(fmaxf(mins[r], 0.0f), 15.0f);
        float e = pv[r] - dm;
        acc = fmaf(e, e, acc);
    }
#pragma unroll
    for (int o = 16; o > 0; o >>= 1) acc += __shfl_xor_sync(0xffffffffu, acc, o);
    if ((t & 31) == 0) wsum[t >> 5] = acc;
    __syncthreads();
    if (t == 0) {
        float s = 0.0f;
#pragma unroll
        for (int k = 0; k < 8; k++) s += wsum[k];
        g_part[b * 64 + tile] = (double)s;
    }

    // Last-block final reduction (fixed order -> deterministic).
    __shared__ double sd[256];
    __shared__ unsigned is_last;
    __threadfence();
    if (t == 0) is_last = (atomicAdd(&g_ctr, 1u) == 255u);
    __syncthreads();
    if (!is_last) return;
    __threadfence();
    sd[t] = g_part[t];
    __syncthreads();
    for (int o = 128; o > 0; o >>= 1) {
        if (t < o) sd[t] += sd[t + o];
        __syncthreads();
    }
    if (t == 0) {
        out[0] = (float)(sd[0] / (double)(BB * HH * WW));
        g_ctr = 0;  // reset for next graph replay
    }
}

extern "C" void kernel_launch(void* const* d_in, const int* in_sizes, int n_in,
                              void* d_out, int out_size) {
    const float* pred = (const float*)d_in[0];      // (4,1,256,256)
    const float* node_pos = (const float*)d_in[1];  // (4,256,2)
    const float* widths = (const float*)d_in[2];    // (4,256)
    (void)in_sizes; (void)n_in; (void)out_size;

    conv_kernel<<<dim3(8, 16, BB), 256>>>(pred);
    snake_kernel<<<BB, 256>>>(node_pos, widths);
    render_kernel<<<dim3(64, BB), 256>>>(pred, (float*)d_out);
}